// round 12
// baseline (speedup 1.0000x reference)
#include <cuda_runtime.h>
#include <cstdint>

// Problem constants
#define BATCH   16
#define TLEN    4096
#define KW      15

// Tiling
#define TT      256      // time tile per CTA
#define NTHREADS 256     // 8 warps; each warp: 2 m16 tiles (32 t)
#define XROW    296      // smem words per channel row; 296 % 32 == 8 -> A loads
                         // hit banks (8*tig + gid) = all-distinct (conflict-free)
#define NW4     68       // float4 chunks per window (272 words = [t0-8, t0+TT+8))

// ---------------------------------------------------------------------------
// Intermediate activation buffers (static device globals; no runtime alloc)
// ---------------------------------------------------------------------------
__device__ float g_h1[(size_t)BATCH * 512 * TLEN];
__device__ float g_h2[(size_t)BATCH * 256 * TLEN];
__device__ float g_h3[(size_t)BATCH * 256 * TLEN];
__device__ float g_h4[(size_t)BATCH * 128 * TLEN];
__device__ float g_h5[(size_t)BATCH *  64 * TLEN];
__device__ float g_h6[(size_t)BATCH *  32 * TLEN];
__device__ float g_h7[(size_t)BATCH *  16 * TLEN];

// ---------------------------------------------------------------------------
// tf32 helpers
// ---------------------------------------------------------------------------
__device__ __forceinline__ uint32_t tf32_rna(float x) {
    uint32_t r; asm("cvt.rna.tf32.f32 %0, %1;" : "=r"(r) : "f"(x)); return r;
}
// D += A(16x8 tf32, row-major) * B(8x8 tf32, col-major), fp32 accumulate
__device__ __forceinline__ void mma_tf32(float& d0, float& d1, float& d2, float& d3,
                                         uint32_t a0, uint32_t a1, uint32_t a2, uint32_t a3,
                                         uint32_t b0, uint32_t b1) {
    asm("mma.sync.aligned.m16n8k8.row.col.f32.tf32.tf32.f32 "
        "{%0,%1,%2,%3}, {%4,%5,%6,%7}, {%8,%9}, {%0,%1,%2,%3};"
        : "+f"(d0), "+f"(d1), "+f"(d2), "+f"(d3)
        : "r"(a0), "r"(a1), "r"(a2), "r"(a3), "r"(b0), "r"(b1));
}
__device__ __forceinline__ uint32_t f2u(float x) { return __float_as_uint(x); }

// ---------------------------------------------------------------------------
// Grouped conv1d K=15 SAME via tensor-core tf32 MMA (split-precision, 3 MMAs).
//   D[t, oc] = sum_{ci, tap} x[ci][t + tap - 7] * W[oc][ci][tap]
// Per (ci-block of 8, tap): one m16n8k8 triple (hi*hi + hi*lo + lo*hi) per
// 16-t tile. A = x window fragment (t rows, ci cols); B = W^T (ci rows, oc
// cols). x split hi/lo at staging (hi = tf32_rna(x), lo = tf32_rna(x - hi))
// -> fp32-class accuracy. Warp w owns t tiles {2w, 2w+1}.
// SMEM: xhi[CINP][XROW] | xlo[CINP][XROW] | whi[15*CINP*8] | wlo[...] | bias
// A-fragment loads and B loads both provably bank-conflict-free (see XROW).
// ---------------------------------------------------------------------------
template<int CINP, int CIN, int C0, bool ACT>
__global__ __launch_bounds__(NTHREADS, 3)
void gconv_mma_kernel(const float* __restrict__ in0, long long bs0,
                      const float* __restrict__ in1, long long bs1,
                      const float* __restrict__ W,
                      const float* __restrict__ bias,
                      float* __restrict__ out, int G)
{
    extern __shared__ float smem[];
    float* sxhi = smem;                        // CINP * XROW
    float* sxlo = sxhi + CINP * XROW;          // CINP * XROW
    float* swhi = sxlo + CINP * XROW;          // 15 * CINP * 8
    float* swlo = swhi + 15 * CINP * 8;        // 15 * CINP * 8
    float* sb   = swlo + 15 * CINP * 8;        // 8

    const int b   = blockIdx.z;
    const int g   = blockIdx.y;
    const int t0  = blockIdx.x * TT;
    const int tid = threadIdx.x;
    const int warp = tid >> 5, lane = tid & 31;
    const int gid = lane >> 2;                 // 0..7
    const int tig = lane & 3;                  // 0..3

    // ---- stage split weights: swhi/swlo[(tap*CINP + ci)*8 + oc] ----
    for (int i = tid; i < 8 * CINP * KW; i += NTHREADS) {
        int oc  = i / (CINP * KW);
        int r   = i - oc * (CINP * KW);
        int ci  = r / KW;
        int tap = r - ci * KW;
        float w = 0.0f;
        if (ci < CIN)
            w = W[((long long)g * 8 * CIN + (long long)oc * CIN + ci) * KW + tap];
        float hi = __uint_as_float(tf32_rna(w));
        float lo = __uint_as_float(tf32_rna(w - hi));
        int d = (tap * CINP + ci) * 8 + oc;
        swhi[d] = hi;
        swlo[d] = lo;
    }
    if (tid < 8) sb[tid] = bias[g * 8 + tid];

    // ---- stage split x window [t0-8, t0+TT+8) per channel ----
    for (int idx = tid; idx < CINP * NW4; idx += NTHREADS) {
        int cl = idx / NW4, j = idx - cl * NW4;
        int t  = t0 - 8 + 4 * j;
        float4 v = make_float4(0.f, 0.f, 0.f, 0.f);
        if (cl < CIN) {
            const float* src;
            if (C0 == CIN || cl < C0)
                src = in0 + (long long)b * bs0 + (long long)(g * C0 + cl) * TLEN;
            else
                src = in1 + (long long)b * bs1 + (long long)(g * (CIN - C0) + (cl - C0)) * TLEN;
            if (t >= 0 && t + 3 < TLEN) {
                v = *(const float4*)(src + t);
            } else {
                if (t     >= 0 && t     < TLEN) v.x = src[t];
                if (t + 1 >= 0 && t + 1 < TLEN) v.y = src[t + 1];
                if (t + 2 >= 0 && t + 2 < TLEN) v.z = src[t + 2];
                if (t + 3 >= 0 && t + 3 < TLEN) v.w = src[t + 3];
            }
        }
        float h0 = __uint_as_float(tf32_rna(v.x));
        float h1 = __uint_as_float(tf32_rna(v.y));
        float h2 = __uint_as_float(tf32_rna(v.z));
        float h3 = __uint_as_float(tf32_rna(v.w));
        float l0 = __uint_as_float(tf32_rna(v.x - h0));
        float l1 = __uint_as_float(tf32_rna(v.y - h1));
        float l2 = __uint_as_float(tf32_rna(v.z - h2));
        float l3 = __uint_as_float(tf32_rna(v.w - h3));
        int base = cl * XROW + 4 * j;
        *(float4*)&sxhi[base] = make_float4(h0, h1, h2, h3);
        *(float4*)&sxlo[base] = make_float4(l0, l1, l2, l3);
    }
    __syncthreads();

    // ---- compute: D[2 tiles][4 regs] ----
    float d00 = 0.f, d01 = 0.f, d02 = 0.f, d03 = 0.f;
    float d10 = 0.f, d11 = 0.f, d12 = 0.f, d13 = 0.f;

#pragma unroll 1
    for (int cib = 0; cib < CINP / 8; cib++) {
#pragma unroll
        for (int tap = 0; tap < KW; tap++) {
            int wb = (tap * CINP + cib * 8) * 8;
            uint32_t bh0 = f2u(swhi[wb + tig * 8 + gid]);
            uint32_t bh1 = f2u(swhi[wb + (tig + 4) * 8 + gid]);
            uint32_t bl0 = f2u(swlo[wb + tig * 8 + gid]);
            uint32_t bl1 = f2u(swlo[wb + (tig + 4) * 8 + gid]);

            // A fragment smem offset: (cib*8 + col)*XROW + (tbase + row + tap + 1)
            int ab = (cib * 8 + tig) * XROW + warp * 32 + gid + tap + 1;

            {   // tile 0: t rows [warp*32, +16)
                uint32_t ah0 = f2u(sxhi[ab]);
                uint32_t ah1 = f2u(sxhi[ab + 8]);
                uint32_t ah2 = f2u(sxhi[ab + 4 * XROW]);
                uint32_t ah3 = f2u(sxhi[ab + 4 * XROW + 8]);
                uint32_t al0 = f2u(sxlo[ab]);
                uint32_t al1 = f2u(sxlo[ab + 8]);
                uint32_t al2 = f2u(sxlo[ab + 4 * XROW]);
                uint32_t al3 = f2u(sxlo[ab + 4 * XROW + 8]);
                mma_tf32(d00, d01, d02, d03, ah0, ah1, ah2, ah3, bh0, bh1);
                mma_tf32(d00, d01, d02, d03, ah0, ah1, ah2, ah3, bl0, bl1);
                mma_tf32(d00, d01, d02, d03, al0, al1, al2, al3, bh0, bh1);
            }
            {   // tile 1: t rows [warp*32+16, +16)
                int ab1 = ab + 16;
                uint32_t ah0 = f2u(sxhi[ab1]);
                uint32_t ah1 = f2u(sxhi[ab1 + 8]);
                uint32_t ah2 = f2u(sxhi[ab1 + 4 * XROW]);
                uint32_t ah3 = f2u(sxhi[ab1 + 4 * XROW + 8]);
                uint32_t al0 = f2u(sxlo[ab1]);
                uint32_t al1 = f2u(sxlo[ab1 + 8]);
                uint32_t al2 = f2u(sxlo[ab1 + 4 * XROW]);
                uint32_t al3 = f2u(sxlo[ab1 + 4 * XROW + 8]);
                mma_tf32(d10, d11, d12, d13, ah0, ah1, ah2, ah3, bh0, bh1);
                mma_tf32(d10, d11, d12, d13, ah0, ah1, ah2, ah3, bl0, bl1);
                mma_tf32(d10, d11, d12, d13, al0, al1, al2, al3, bh0, bh1);
            }
        }
    }

    // ---- epilogue: bias + leaky relu; D[row, col] -> out[oc=col][t0+tbase+row]
    const float bv0 = sb[2 * tig];
    const float bv1 = sb[2 * tig + 1];
    float* obase = out + ((long long)(b * G + g) * 8) * TLEN + t0 + warp * 32;
    float* o0 = obase + (long long)(2 * tig) * TLEN;
    float* o1 = obase + (long long)(2 * tig + 1) * TLEN;

    auto act = [](float v, bool on) { return on ? (v > 0.f ? v : 0.01f * v) : v; };
    float v;
    v = d00 + bv0; o0[gid]          = act(v, ACT);
    v = d01 + bv1; o1[gid]          = act(v, ACT);
    v = d02 + bv0; o0[gid + 8]      = act(v, ACT);
    v = d03 + bv1; o1[gid + 8]      = act(v, ACT);
    v = d10 + bv0; o0[gid + 16]     = act(v, ACT);
    v = d11 + bv1; o1[gid + 16]     = act(v, ACT);
    v = d12 + bv0; o0[gid + 24]     = act(v, ACT);
    v = d13 + bv1; o1[gid + 24]     = act(v, ACT);
}

// ---------------------------------------------------------------------------
// Root: 1x1 conv over 16 channels -> 1 channel (no activation)
// ---------------------------------------------------------------------------
__global__ void root_kernel(const float* __restrict__ h,
                            const float* __restrict__ w,
                            const float* __restrict__ bias,
                            float* __restrict__ out)
{
    int idx = blockIdx.x * blockDim.x + threadIdx.x;
    if (idx >= BATCH * TLEN) return;
    int b = idx / TLEN;
    int t = idx - b * TLEN;
    const float* hp = h + (long long)b * 16 * TLEN + t;
    float s = bias[0];
#pragma unroll
    for (int c = 0; c < 16; c++)
        s = fmaf(__ldg(&w[c]), hp[(long long)c * TLEN], s);
    out[idx] = s;
}

// ---------------------------------------------------------------------------
// Launch
// ---------------------------------------------------------------------------
static inline int smem_bytes(int cinp) {
    return (2 * cinp * XROW + 2 * 15 * cinp * 8 + 8) * 4;
}

extern "C" void kernel_launch(void* const* d_in, const int* in_sizes, int n_in,
                              void* d_out, int out_size)
{
    const float* x      = (const float*)d_in[0];
    const float* W_leaf = (const float*)d_in[1];
    const float* b_leaf = (const float*)d_in[2];
    const float* W_int0 = (const float*)d_in[3];
    const float* b_int0 = (const float*)d_in[4];
    const float* W_br   = (const float*)d_in[5];
    const float* b_br   = (const float*)d_in[6];
    const float* W_int1 = (const float*)d_in[7];
    const float* b_int1 = (const float*)d_in[8];
    const float* W_int2 = (const float*)d_in[9];
    const float* b_int2 = (const float*)d_in[10];
    const float* W_int3 = (const float*)d_in[11];
    const float* b_int3 = (const float*)d_in[12];
    const float* W_int4 = (const float*)d_in[13];
    const float* b_int4 = (const float*)d_in[14];
    const float* W_root = (const float*)d_in[15];
    const float* b_root = (const float*)d_in[16];
    float* out = (float*)d_out;

    float *h1, *h2, *h3, *h4, *h5, *h6, *h7;
    cudaGetSymbolAddress((void**)&h1, g_h1);
    cudaGetSymbolAddress((void**)&h2, g_h2);
    cudaGetSymbolAddress((void**)&h3, g_h3);
    cudaGetSymbolAddress((void**)&h4, g_h4);
    cudaGetSymbolAddress((void**)&h5, g_h5);
    cudaGetSymbolAddress((void**)&h6, g_h6);
    cudaGetSymbolAddress((void**)&h7, g_h7);

    const int TB = TLEN / TT;   // 16 tiles along T
    const long long BSX = (long long)1536 * TLEN;

    const int SM24 = smem_bytes(24);   // ~80 KB -> 2 CTAs/SM (leaf)
    const int SM16 = smem_bytes(16);   // ~53 KB -> 3 CTAs/SM

    cudaFuncSetAttribute(gconv_mma_kernel<24, 20, 20, true>,
                         cudaFuncAttributeMaxDynamicSharedMemorySize, SM24);
    cudaFuncSetAttribute(gconv_mma_kernel<16, 16, 16, true>,
                         cudaFuncAttributeMaxDynamicSharedMemorySize, SM16);
    cudaFuncSetAttribute(gconv_mma_kernel<16, 16, 8, true>,
                         cudaFuncAttributeMaxDynamicSharedMemorySize, SM16);

    // 1. leaf: 64 groups, 20 in/group (padded to 24), 8 out/group
    gconv_mma_kernel<24, 20, 20, true><<<dim3(TB, 64, BATCH), NTHREADS, SM24>>>(
        x, BSX, nullptr, 0, W_leaf, b_leaf, h1, 64);

    // 2. int0: 32 groups, 16 in/group (from 512 ch)
    gconv_mma_kernel<16, 16, 16, true><<<dim3(TB, 32, BATCH), NTHREADS, SM16>>>(
        h1, (long long)512 * TLEN, nullptr, 0, W_int0, b_int0, h2, 32);

    // 3. br: 32 groups, in/group = 8 (h2) + 8 (syn = x channels 1280..1535)
    gconv_mma_kernel<16, 16, 8, true><<<dim3(TB, 32, BATCH), NTHREADS, SM16>>>(
        h2, (long long)256 * TLEN,
        x + (long long)1280 * TLEN, BSX,
        W_br, b_br, h3, 32);

    // 4. int1: 16 groups (256 -> 128)
    gconv_mma_kernel<16, 16, 16, true><<<dim3(TB, 16, BATCH), NTHREADS, SM16>>>(
        h3, (long long)256 * TLEN, nullptr, 0, W_int1, b_int1, h4, 16);

    // 5. int2: 8 groups (128 -> 64)
    gconv_mma_kernel<16, 16, 16, true><<<dim3(TB, 8, BATCH), NTHREADS, SM16>>>(
        h4, (long long)128 * TLEN, nullptr, 0, W_int2, b_int2, h5, 8);

    // 6. int3: 4 groups (64 -> 32)
    gconv_mma_kernel<16, 16, 16, true><<<dim3(TB, 4, BATCH), NTHREADS, SM16>>>(
        h5, (long long)64 * TLEN, nullptr, 0, W_int3, b_int3, h6, 4);

    // 7. int4: 2 groups (32 -> 16)
    gconv_mma_kernel<16, 16, 16, true><<<dim3(TB, 2, BATCH), NTHREADS, SM16>>>(
        h6, (long long)32 * TLEN, nullptr, 0, W_int4, b_int4, h7, 2);

    // 8. root: 1x1 conv 16 -> 1
    root_kernel<<<(BATCH * TLEN + 255) / 256, 256>>>(h7, W_root, b_root, out);
}

// round 13
// speedup vs baseline: 1.0071x; 1.0071x over previous
#include <cuda_runtime.h>
#include <cstdint>

// Problem constants
#define BATCH   16
#define TLEN    4096
#define KW      15

// Tiling
#define TT      256      // time tile per CTA
#define NTHREADS 256     // 8 warps; each warp: 2 m16 tiles (32 t)
#define XROW    296      // smem words per channel row; 296 % 32 == 8 -> A loads
                         // hit banks (8*tig + gid) = all-distinct (conflict-free)
#define NW4     68       // float4 chunks per window (272 words = [t0-8, t0+TT+8))

// ---------------------------------------------------------------------------
// Intermediate activation buffers (static device globals; no runtime alloc)
// ---------------------------------------------------------------------------
__device__ float g_h1[(size_t)BATCH * 512 * TLEN];
__device__ float g_h2[(size_t)BATCH * 256 * TLEN];
__device__ float g_h3[(size_t)BATCH * 256 * TLEN];
__device__ float g_h4[(size_t)BATCH * 128 * TLEN];
__device__ float g_h5[(size_t)BATCH *  64 * TLEN];
__device__ float g_h6[(size_t)BATCH *  32 * TLEN];
__device__ float g_h7[(size_t)BATCH *  16 * TLEN];

// ---------------------------------------------------------------------------
// tf32 helpers
// ---------------------------------------------------------------------------
__device__ __forceinline__ uint32_t tf32_rna(float x) {
    uint32_t r; asm("cvt.rna.tf32.f32 %0, %1;" : "=r"(r) : "f"(x)); return r;
}
// D += A(16x8 tf32, row-major) * B(8x8 tf32, col-major), fp32 accumulate
__device__ __forceinline__ void mma_tf32(float& d0, float& d1, float& d2, float& d3,
                                         uint32_t a0, uint32_t a1, uint32_t a2, uint32_t a3,
                                         uint32_t b0, uint32_t b1) {
    asm("mma.sync.aligned.m16n8k8.row.col.f32.tf32.tf32.f32 "
        "{%0,%1,%2,%3}, {%4,%5,%6,%7}, {%8,%9}, {%0,%1,%2,%3};"
        : "+f"(d0), "+f"(d1), "+f"(d2), "+f"(d3)
        : "r"(a0), "r"(a1), "r"(a2), "r"(a3), "r"(b0), "r"(b1));
}
__device__ __forceinline__ uint32_t f2u(float x) { return __float_as_uint(x); }

// ---------------------------------------------------------------------------
// Grouped conv1d K=15 SAME via tensor-core tf32 MMA (split-precision, 3 MMAs).
//   D[t, oc] = sum_{ci, tap} x[ci][t + tap - 7] * W[oc][ci][tap]
// Per (ci-block of 8, tap): one m16n8k8 triple (hi*hi + hi*lo + lo*hi) per
// 16-t tile. A = x window fragment (t rows, ci cols); B = W^T (ci rows, oc
// cols). x split hi/lo at staging (hi = tf32_rna(x), lo = tf32_rna(x - hi))
// -> fp32-class accuracy. Warp w owns t tiles {2w, 2w+1}.
// SMEM: xhi[CINP][XROW] | xlo[CINP][XROW] | whi[15*CINP*8] | wlo[...] | bias
// A-fragment loads and B loads both provably bank-conflict-free (see XROW).
// ---------------------------------------------------------------------------
template<int CINP, int CIN, int C0, bool ACT>
__global__ __launch_bounds__(NTHREADS, 3)
void gconv_mma_kernel(const float* __restrict__ in0, long long bs0,
                      const float* __restrict__ in1, long long bs1,
                      const float* __restrict__ W,
                      const float* __restrict__ bias,
                      float* __restrict__ out, int G)
{
    extern __shared__ float smem[];
    float* sxhi = smem;                        // CINP * XROW
    float* sxlo = sxhi + CINP * XROW;          // CINP * XROW
    float* swhi = sxlo + CINP * XROW;          // 15 * CINP * 8
    float* swlo = swhi + 15 * CINP * 8;        // 15 * CINP * 8
    float* sb   = swlo + 15 * CINP * 8;        // 8

    const int b   = blockIdx.z;
    const int g   = blockIdx.y;
    const int t0  = blockIdx.x * TT;
    const int tid = threadIdx.x;
    const int warp = tid >> 5, lane = tid & 31;
    const int gid = lane >> 2;                 // 0..7
    const int tig = lane & 3;                  // 0..3

    // ---- stage split weights: swhi/swlo[(tap*CINP + ci)*8 + oc] ----
    for (int i = tid; i < 8 * CINP * KW; i += NTHREADS) {
        int oc  = i / (CINP * KW);
        int r   = i - oc * (CINP * KW);
        int ci  = r / KW;
        int tap = r - ci * KW;
        float w = 0.0f;
        if (ci < CIN)
            w = W[((long long)g * 8 * CIN + (long long)oc * CIN + ci) * KW + tap];
        float hi = __uint_as_float(tf32_rna(w));
        float lo = __uint_as_float(tf32_rna(w - hi));
        int d = (tap * CINP + ci) * 8 + oc;
        swhi[d] = hi;
        swlo[d] = lo;
    }
    if (tid < 8) sb[tid] = bias[g * 8 + tid];

    // ---- stage split x window [t0-8, t0+TT+8) per channel ----
    for (int idx = tid; idx < CINP * NW4; idx += NTHREADS) {
        int cl = idx / NW4, j = idx - cl * NW4;
        int t  = t0 - 8 + 4 * j;
        float4 v = make_float4(0.f, 0.f, 0.f, 0.f);
        if (cl < CIN) {
            const float* src;
            if (C0 == CIN || cl < C0)
                src = in0 + (long long)b * bs0 + (long long)(g * C0 + cl) * TLEN;
            else
                src = in1 + (long long)b * bs1 + (long long)(g * (CIN - C0) + (cl - C0)) * TLEN;
            if (t >= 0 && t + 3 < TLEN) {
                v = *(const float4*)(src + t);
            } else {
                if (t     >= 0 && t     < TLEN) v.x = src[t];
                if (t + 1 >= 0 && t + 1 < TLEN) v.y = src[t + 1];
                if (t + 2 >= 0 && t + 2 < TLEN) v.z = src[t + 2];
                if (t + 3 >= 0 && t + 3 < TLEN) v.w = src[t + 3];
            }
        }
        float h0 = __uint_as_float(tf32_rna(v.x));
        float h1 = __uint_as_float(tf32_rna(v.y));
        float h2 = __uint_as_float(tf32_rna(v.z));
        float h3 = __uint_as_float(tf32_rna(v.w));
        float l0 = __uint_as_float(tf32_rna(v.x - h0));
        float l1 = __uint_as_float(tf32_rna(v.y - h1));
        float l2 = __uint_as_float(tf32_rna(v.z - h2));
        float l3 = __uint_as_float(tf32_rna(v.w - h3));
        int base = cl * XROW + 4 * j;
        *(float4*)&sxhi[base] = make_float4(h0, h1, h2, h3);
        *(float4*)&sxlo[base] = make_float4(l0, l1, l2, l3);
    }
    __syncthreads();

    // ---- compute: D[2 tiles][4 regs] ----
    float d00 = 0.f, d01 = 0.f, d02 = 0.f, d03 = 0.f;
    float d10 = 0.f, d11 = 0.f, d12 = 0.f, d13 = 0.f;

#pragma unroll 1
    for (int cib = 0; cib < CINP / 8; cib++) {
#pragma unroll
        for (int tap = 0; tap < KW; tap++) {
            int wb = (tap * CINP + cib * 8) * 8;
            uint32_t bh0 = f2u(swhi[wb + tig * 8 + gid]);
            uint32_t bh1 = f2u(swhi[wb + (tig + 4) * 8 + gid]);
            uint32_t bl0 = f2u(swlo[wb + tig * 8 + gid]);
            uint32_t bl1 = f2u(swlo[wb + (tig + 4) * 8 + gid]);

            // A fragment smem offset: (cib*8 + col)*XROW + (tbase + row + tap + 1)
            int ab = (cib * 8 + tig) * XROW + warp * 32 + gid + tap + 1;

            {   // tile 0: t rows [warp*32, +16)
                uint32_t ah0 = f2u(sxhi[ab]);
                uint32_t ah1 = f2u(sxhi[ab + 8]);
                uint32_t ah2 = f2u(sxhi[ab + 4 * XROW]);
                uint32_t ah3 = f2u(sxhi[ab + 4 * XROW + 8]);
                uint32_t al0 = f2u(sxlo[ab]);
                uint32_t al1 = f2u(sxlo[ab + 8]);
                uint32_t al2 = f2u(sxlo[ab + 4 * XROW]);
                uint32_t al3 = f2u(sxlo[ab + 4 * XROW + 8]);
                mma_tf32(d00, d01, d02, d03, ah0, ah1, ah2, ah3, bh0, bh1);
                mma_tf32(d00, d01, d02, d03, ah0, ah1, ah2, ah3, bl0, bl1);
                mma_tf32(d00, d01, d02, d03, al0, al1, al2, al3, bh0, bh1);
            }
            {   // tile 1: t rows [warp*32+16, +16)
                int ab1 = ab + 16;
                uint32_t ah0 = f2u(sxhi[ab1]);
                uint32_t ah1 = f2u(sxhi[ab1 + 8]);
                uint32_t ah2 = f2u(sxhi[ab1 + 4 * XROW]);
                uint32_t ah3 = f2u(sxhi[ab1 + 4 * XROW + 8]);
                uint32_t al0 = f2u(sxlo[ab1]);
                uint32_t al1 = f2u(sxlo[ab1 + 8]);
                uint32_t al2 = f2u(sxlo[ab1 + 4 * XROW]);
                uint32_t al3 = f2u(sxlo[ab1 + 4 * XROW + 8]);
                mma_tf32(d10, d11, d12, d13, ah0, ah1, ah2, ah3, bh0, bh1);
                mma_tf32(d10, d11, d12, d13, ah0, ah1, ah2, ah3, bl0, bl1);
                mma_tf32(d10, d11, d12, d13, al0, al1, al2, al3, bh0, bh1);
            }
        }
    }

    // ---- epilogue: bias + leaky relu; D[row, col] -> out[oc=col][t0+tbase+row]
    const float bv0 = sb[2 * tig];
    const float bv1 = sb[2 * tig + 1];
    float* obase = out + ((long long)(b * G + g) * 8) * TLEN + t0 + warp * 32;
    float* o0 = obase + (long long)(2 * tig) * TLEN;
    float* o1 = obase + (long long)(2 * tig + 1) * TLEN;

    auto act = [](float v, bool on) { return on ? (v > 0.f ? v : 0.01f * v) : v; };
    float v;
    v = d00 + bv0; o0[gid]          = act(v, ACT);
    v = d01 + bv1; o1[gid]          = act(v, ACT);
    v = d02 + bv0; o0[gid + 8]      = act(v, ACT);
    v = d03 + bv1; o1[gid + 8]      = act(v, ACT);
    v = d10 + bv0; o0[gid + 16]     = act(v, ACT);
    v = d11 + bv1; o1[gid + 16]     = act(v, ACT);
    v = d12 + bv0; o0[gid + 24]     = act(v, ACT);
    v = d13 + bv1; o1[gid + 24]     = act(v, ACT);
}

// ---------------------------------------------------------------------------
// Root: 1x1 conv over 16 channels -> 1 channel (no activation)
// ---------------------------------------------------------------------------
__global__ void root_kernel(const float* __restrict__ h,
                            const float* __restrict__ w,
                            const float* __restrict__ bias,
                            float* __restrict__ out)
{
    int idx = blockIdx.x * blockDim.x + threadIdx.x;
    if (idx >= BATCH * TLEN) return;
    int b = idx / TLEN;
    int t = idx - b * TLEN;
    const float* hp = h + (long long)b * 16 * TLEN + t;
    float s = bias[0];
#pragma unroll
    for (int c = 0; c < 16; c++)
        s = fmaf(__ldg(&w[c]), hp[(long long)c * TLEN], s);
    out[idx] = s;
}

// ---------------------------------------------------------------------------
// Launch
// ---------------------------------------------------------------------------
static inline int smem_bytes(int cinp) {
    return (2 * cinp * XROW + 2 * 15 * cinp * 8 + 8) * 4;
}

extern "C" void kernel_launch(void* const* d_in, const int* in_sizes, int n_in,
                              void* d_out, int out_size)
{
    const float* x      = (const float*)d_in[0];
    const float* W_leaf = (const float*)d_in[1];
    const float* b_leaf = (const float*)d_in[2];
    const float* W_int0 = (const float*)d_in[3];
    const float* b_int0 = (const float*)d_in[4];
    const float* W_br   = (const float*)d_in[5];
    const float* b_br   = (const float*)d_in[6];
    const float* W_int1 = (const float*)d_in[7];
    const float* b_int1 = (const float*)d_in[8];
    const float* W_int2 = (const float*)d_in[9];
    const float* b_int2 = (const float*)d_in[10];
    const float* W_int3 = (const float*)d_in[11];
    const float* b_int3 = (const float*)d_in[12];
    const float* W_int4 = (const float*)d_in[13];
    const float* b_int4 = (const float*)d_in[14];
    const float* W_root = (const float*)d_in[15];
    const float* b_root = (const float*)d_in[16];
    float* out = (float*)d_out;

    float *h1, *h2, *h3, *h4, *h5, *h6, *h7;
    cudaGetSymbolAddress((void**)&h1, g_h1);
    cudaGetSymbolAddress((void**)&h2, g_h2);
    cudaGetSymbolAddress((void**)&h3, g_h3);
    cudaGetSymbolAddress((void**)&h4, g_h4);
    cudaGetSymbolAddress((void**)&h5, g_h5);
    cudaGetSymbolAddress((void**)&h6, g_h6);
    cudaGetSymbolAddress((void**)&h7, g_h7);

    const int TB = TLEN / TT;   // 16 tiles along T
    const long long BSX = (long long)1536 * TLEN;

    const int SM24 = smem_bytes(24);   // ~80 KB -> 2 CTAs/SM (leaf)
    const int SM16 = smem_bytes(16);   // ~53 KB -> 3 CTAs/SM

    cudaFuncSetAttribute(gconv_mma_kernel<24, 20, 20, true>,
                         cudaFuncAttributeMaxDynamicSharedMemorySize, SM24);
    cudaFuncSetAttribute(gconv_mma_kernel<16, 16, 16, true>,
                         cudaFuncAttributeMaxDynamicSharedMemorySize, SM16);
    cudaFuncSetAttribute(gconv_mma_kernel<16, 16, 8, true>,
                         cudaFuncAttributeMaxDynamicSharedMemorySize, SM16);

    // 1. leaf: 64 groups, 20 in/group (padded to 24), 8 out/group
    gconv_mma_kernel<24, 20, 20, true><<<dim3(TB, 64, BATCH), NTHREADS, SM24>>>(
        x, BSX, nullptr, 0, W_leaf, b_leaf, h1, 64);

    // 2. int0: 32 groups, 16 in/group (from 512 ch)
    gconv_mma_kernel<16, 16, 16, true><<<dim3(TB, 32, BATCH), NTHREADS, SM16>>>(
        h1, (long long)512 * TLEN, nullptr, 0, W_int0, b_int0, h2, 32);

    // 3. br: 32 groups, in/group = 8 (h2) + 8 (syn = x channels 1280..1535)
    gconv_mma_kernel<16, 16, 8, true><<<dim3(TB, 32, BATCH), NTHREADS, SM16>>>(
        h2, (long long)256 * TLEN,
        x + (long long)1280 * TLEN, BSX,
        W_br, b_br, h3, 32);

    // 4. int1: 16 groups (256 -> 128)
    gconv_mma_kernel<16, 16, 16, true><<<dim3(TB, 16, BATCH), NTHREADS, SM16>>>(
        h3, (long long)256 * TLEN, nullptr, 0, W_int1, b_int1, h4, 16);

    // 5. int2: 8 groups (128 -> 64)
    gconv_mma_kernel<16, 16, 16, true><<<dim3(TB, 8, BATCH), NTHREADS, SM16>>>(
        h4, (long long)128 * TLEN, nullptr, 0, W_int2, b_int2, h5, 8);

    // 6. int3: 4 groups (64 -> 32)
    gconv_mma_kernel<16, 16, 16, true><<<dim3(TB, 4, BATCH), NTHREADS, SM16>>>(
        h5, (long long)64 * TLEN, nullptr, 0, W_int3, b_int3, h6, 4);

    // 7. int4: 2 groups (32 -> 16)
    gconv_mma_kernel<16, 16, 16, true><<<dim3(TB, 2, BATCH), NTHREADS, SM16>>>(
        h6, (long long)32 * TLEN, nullptr, 0, W_int4, b_int4, h7, 2);

    // 8. root: 1x1 conv 16 -> 1
    root_kernel<<<(BATCH * TLEN + 255) / 256, 256>>>(h7, W_root, b_root, out);
}

// round 14
// speedup vs baseline: 1.0715x; 1.0639x over previous
#include <cuda_runtime.h>
#include <cstdint>

// Problem constants
#define BATCH   16
#define TLEN    4096
#define KW      15

// Tiling
#define TT      256      // time tile per CTA
#define NTHREADS 256     // 8 warps; each warp: 2 m16 tiles (32 t)
#define TROWS   272      // staged t' rows: [t0-8, t0+TT+8)
#define NTQ     68       // t-quads (TROWS/4)

typedef unsigned long long u64;

// ---------------------------------------------------------------------------
// Intermediate activation buffers (static device globals; no runtime alloc)
// ---------------------------------------------------------------------------
__device__ float g_h1[(size_t)BATCH * 512 * TLEN];
__device__ float g_h2[(size_t)BATCH * 256 * TLEN];
__device__ float g_h3[(size_t)BATCH * 256 * TLEN];
__device__ float g_h4[(size_t)BATCH * 128 * TLEN];
__device__ float g_h5[(size_t)BATCH *  64 * TLEN];
__device__ float g_h6[(size_t)BATCH *  32 * TLEN];
__device__ float g_h7[(size_t)BATCH *  16 * TLEN];

// ---------------------------------------------------------------------------
// tf32 / mma / ldmatrix helpers
// ---------------------------------------------------------------------------
__device__ __forceinline__ uint32_t tf32_rna(float x) {
    uint32_t r; asm("cvt.rna.tf32.f32 %0, %1;" : "=r"(r) : "f"(x)); return r;
}
__device__ __forceinline__ void mma_tf32(float& d0, float& d1, float& d2, float& d3,
                                         uint32_t a0, uint32_t a1, uint32_t a2, uint32_t a3,
                                         uint32_t b0, uint32_t b1) {
    asm("mma.sync.aligned.m16n8k8.row.col.f32.tf32.tf32.f32 "
        "{%0,%1,%2,%3}, {%4,%5,%6,%7}, {%8,%9}, {%0,%1,%2,%3};"
        : "+f"(d0), "+f"(d1), "+f"(d2), "+f"(d3)
        : "r"(a0), "r"(a1), "r"(a2), "r"(a3), "r"(b0), "r"(b1));
}
__device__ __forceinline__ void ldsm_x4(uint32_t& r0, uint32_t& r1,
                                        uint32_t& r2, uint32_t& r3, uint32_t addr) {
    asm volatile("ldmatrix.sync.aligned.m8n8.x4.shared.b16 {%0,%1,%2,%3}, [%4];"
                 : "=r"(r0), "=r"(r1), "=r"(r2), "=r"(r3) : "r"(addr));
}
__device__ __forceinline__ uint32_t f2u(float x) { return __float_as_uint(x); }

// ---------------------------------------------------------------------------
// Grouped conv1d K=15 SAME via tf32 MMA (split precision, 3 MMAs) with
// ldmatrix-fed A fragments.
//   D[t, oc] = sum_{ci, tap} x[ci][t + tap - 7] * W[oc][ci][tap]
// x staged TRANSPOSED: xT[t'][ci], t' = t - t0 + 8, rows padded to
// STRIDE = CINP+4 floats so each 8x8 ldmatrix tile is bank-conflict-free.
// A fragment (t rows x 8 ci) for (cib, tap, tile) = ONE ldmatrix.x4 per
// precision image: thread groups 0-7/8-15/16-23/24-31 supply rows
// (r, cihalf) = (0-7,0)/(8-15,0)/(0-7,1)/(8-15,1) -> regs = a0,a1,a2,a3.
// B = W^T fragments, 2 LDS.32 per precision (same as proven R13 layout).
// Split precision: hi*whi + hi*wlo + lo*whi -> fp32-class accuracy.
// Warp w owns t tiles at w*32 and w*32+16.
// ---------------------------------------------------------------------------
template<int CINP, int CIN, int C0, bool ACT>
__global__ __launch_bounds__(NTHREADS, 3)
void gconv_mma_kernel(const float* __restrict__ in0, long long bs0,
                      const float* __restrict__ in1, long long bs1,
                      const float* __restrict__ W,
                      const float* __restrict__ bias,
                      float* __restrict__ out, int G)
{
    constexpr int STRIDE = CINP + 4;           // floats per xT row
    extern __shared__ float smem[];
    float* sxhi = smem;                        // TROWS * STRIDE
    float* sxlo = sxhi + TROWS * STRIDE;       // TROWS * STRIDE
    float* swhi = sxlo + TROWS * STRIDE;       // 15 * CINP * 8
    float* swlo = swhi + 15 * CINP * 8;        // 15 * CINP * 8
    float* sb   = swlo + 15 * CINP * 8;        // 8

    const int b   = blockIdx.z;
    const int g   = blockIdx.y;
    const int t0  = blockIdx.x * TT;
    const int tid = threadIdx.x;
    const int warp = tid >> 5, lane = tid & 31;
    const int gid = lane >> 2;                 // 0..7
    const int tig = lane & 3;                  // 0..3
    const int lrow = ((lane >> 3) & 1) * 8 + (lane & 7);  // ldmatrix row
    const int lcol = (lane >> 4) * 4;                      // ldmatrix ci-half

    // ---- stage split weights: swhi/swlo[(tap*CINP + ci)*8 + oc] ----
    for (int i = tid; i < 8 * CINP * KW; i += NTHREADS) {
        int oc  = i / (CINP * KW);
        int r   = i - oc * (CINP * KW);
        int ci  = r / KW;
        int tap = r - ci * KW;
        float w = 0.0f;
        if (ci < CIN)
            w = W[((long long)g * 8 * CIN + (long long)oc * CIN + ci) * KW + tap];
        float hi = __uint_as_float(tf32_rna(w));
        float lo = __uint_as_float(tf32_rna(w - hi));
        int d = (tap * CINP + ci) * 8 + oc;
        swhi[d] = hi;
        swlo[d] = lo;
    }
    if (tid < 8) sb[tid] = bias[g * 8 + tid];

    // ---- stage x transposed + split: xT[t'][ci] ----
    for (int idx = tid; idx < NTQ * (CINP / 4); idx += NTHREADS) {
        int tc = idx % NTQ;                    // lanes consecutive in t-quad
        int cq = idx / NTQ;
        int tg = t0 - 8 + 4 * tc;
        float4 v[4];
#pragma unroll
        for (int j = 0; j < 4; j++) {
            int ci = cq * 4 + j;
            v[j] = make_float4(0.f, 0.f, 0.f, 0.f);
            if (ci < CIN) {
                const float* src;
                if (C0 == CIN || ci < C0)
                    src = in0 + (long long)b * bs0 + (long long)(g * C0 + ci) * TLEN;
                else
                    src = in1 + (long long)b * bs1 + (long long)(g * (CIN - C0) + (ci - C0)) * TLEN;
                if (tg >= 0 && tg <= TLEN - 4) {
                    v[j] = *(const float4*)(src + tg);
                } else {
                    float* p = (float*)&v[j];
#pragma unroll
                    for (int k = 0; k < 4; k++) {
                        int t = tg + k;
                        if (t >= 0 && t < TLEN) p[k] = src[t];
                    }
                }
            }
        }
        // transpose 4x4, split hi/lo, store rows
#pragma unroll
        for (int k = 0; k < 4; k++) {
            float x0 = ((float*)&v[0])[k];
            float x1 = ((float*)&v[1])[k];
            float x2 = ((float*)&v[2])[k];
            float x3 = ((float*)&v[3])[k];
            float h0 = __uint_as_float(tf32_rna(x0));
            float h1 = __uint_as_float(tf32_rna(x1));
            float h2 = __uint_as_float(tf32_rna(x2));
            float h3 = __uint_as_float(tf32_rna(x3));
            float l0 = __uint_as_float(tf32_rna(x0 - h0));
            float l1 = __uint_as_float(tf32_rna(x1 - h1));
            float l2 = __uint_as_float(tf32_rna(x2 - h2));
            float l3 = __uint_as_float(tf32_rna(x3 - h3));
            int off = (4 * tc + k) * STRIDE + cq * 4;
            *(float4*)(sxhi + off) = make_float4(h0, h1, h2, h3);
            *(float4*)(sxlo + off) = make_float4(l0, l1, l2, l3);
        }
    }
    __syncthreads();

    // ---- compute ----
    float d0[4] = {0.f, 0.f, 0.f, 0.f};       // tile 0 (t rows warp*32 .. +15)
    float d1[4] = {0.f, 0.f, 0.f, 0.f};       // tile 1 (+16)

    // A base addresses (shared space): row = warp*32 + 1 + lrow, col = lcol
    uint32_t axhi = (uint32_t)__cvta_generic_to_shared(sxhi)
                  + (uint32_t)(((warp * 32 + 1 + lrow) * STRIDE + lcol) * 4);
    uint32_t axlo = axhi + (uint32_t)(TROWS * STRIDE * 4);

#pragma unroll 1
    for (int cib = 0; cib < CINP / 8; cib++) {
#pragma unroll
        for (int tap = 0; tap < KW; tap++) {
            int wb = (tap * CINP + cib * 8) * 8;
            uint32_t bh0 = f2u(swhi[wb + tig * 8 + gid]);
            uint32_t bh1 = f2u(swhi[wb + (tig + 4) * 8 + gid]);
            uint32_t bl0 = f2u(swlo[wb + tig * 8 + gid]);
            uint32_t bl1 = f2u(swlo[wb + (tig + 4) * 8 + gid]);

            uint32_t roff = (uint32_t)((tap * STRIDE + cib * 8) * 4);

            {   // tile 0
                uint32_t ah0, ah1, ah2, ah3, al0, al1, al2, al3;
                ldsm_x4(ah0, ah1, ah2, ah3, axhi + roff);
                ldsm_x4(al0, al1, al2, al3, axlo + roff);
                mma_tf32(d0[0], d0[1], d0[2], d0[3], ah0, ah1, ah2, ah3, bh0, bh1);
                mma_tf32(d0[0], d0[1], d0[2], d0[3], ah0, ah1, ah2, ah3, bl0, bl1);
                mma_tf32(d0[0], d0[1], d0[2], d0[3], al0, al1, al2, al3, bh0, bh1);
            }
            {   // tile 1 (+16 t rows)
                uint32_t toff = roff + (uint32_t)(16 * STRIDE * 4);
                uint32_t ah0, ah1, ah2, ah3, al0, al1, al2, al3;
                ldsm_x4(ah0, ah1, ah2, ah3, axhi + toff);
                ldsm_x4(al0, al1, al2, al3, axlo + toff);
                mma_tf32(d1[0], d1[1], d1[2], d1[3], ah0, ah1, ah2, ah3, bh0, bh1);
                mma_tf32(d1[0], d1[1], d1[2], d1[3], ah0, ah1, ah2, ah3, bl0, bl1);
                mma_tf32(d1[0], d1[1], d1[2], d1[3], al0, al1, al2, al3, bh0, bh1);
            }
        }
    }

    // ---- epilogue: bias + leaky relu ----
    const float bv0 = sb[2 * tig];
    const float bv1 = sb[2 * tig + 1];
    float* obase = out + ((long long)(b * G + g) * 8) * TLEN + t0 + warp * 32;
    float* o0 = obase + (long long)(2 * tig) * TLEN;
    float* o1 = obase + (long long)(2 * tig + 1) * TLEN;

    auto act = [](float v, bool on) { return on ? (v > 0.f ? v : 0.01f * v) : v; };
    o0[gid]      = act(d0[0] + bv0, ACT);
    o1[gid]      = act(d0[1] + bv1, ACT);
    o0[gid + 8]  = act(d0[2] + bv0, ACT);
    o1[gid + 8]  = act(d0[3] + bv1, ACT);
    o0[gid + 16] = act(d1[0] + bv0, ACT);
    o1[gid + 16] = act(d1[1] + bv1, ACT);
    o0[gid + 24] = act(d1[2] + bv0, ACT);
    o1[gid + 24] = act(d1[3] + bv1, ACT);
}

// ---------------------------------------------------------------------------
// Root: 1x1 conv over 16 channels -> 1 channel (no activation)
// ---------------------------------------------------------------------------
__global__ void root_kernel(const float* __restrict__ h,
                            const float* __restrict__ w,
                            const float* __restrict__ bias,
                            float* __restrict__ out)
{
    int idx = blockIdx.x * blockDim.x + threadIdx.x;
    if (idx >= BATCH * TLEN) return;
    int b = idx / TLEN;
    int t = idx - b * TLEN;
    const float* hp = h + (long long)b * 16 * TLEN + t;
    float s = bias[0];
#pragma unroll
    for (int c = 0; c < 16; c++)
        s = fmaf(__ldg(&w[c]), hp[(long long)c * TLEN], s);
    out[idx] = s;
}

// ---------------------------------------------------------------------------
// Launch
// ---------------------------------------------------------------------------
static inline int smem_bytes(int cinp) {
    int stride = cinp + 4;
    return (2 * TROWS * stride + 2 * 15 * cinp * 8 + 8) * 4;
}

extern "C" void kernel_launch(void* const* d_in, const int* in_sizes, int n_in,
                              void* d_out, int out_size)
{
    const float* x      = (const float*)d_in[0];
    const float* W_leaf = (const float*)d_in[1];
    const float* b_leaf = (const float*)d_in[2];
    const float* W_int0 = (const float*)d_in[3];
    const float* b_int0 = (const float*)d_in[4];
    const float* W_br   = (const float*)d_in[5];
    const float* b_br   = (const float*)d_in[6];
    const float* W_int1 = (const float*)d_in[7];
    const float* b_int1 = (const float*)d_in[8];
    const float* W_int2 = (const float*)d_in[9];
    const float* b_int2 = (const float*)d_in[10];
    const float* W_int3 = (const float*)d_in[11];
    const float* b_int3 = (const float*)d_in[12];
    const float* W_int4 = (const float*)d_in[13];
    const float* b_int4 = (const float*)d_in[14];
    const float* W_root = (const float*)d_in[15];
    const float* b_root = (const float*)d_in[16];
    float* out = (float*)d_out;

    float *h1, *h2, *h3, *h4, *h5, *h6, *h7;
    cudaGetSymbolAddress((void**)&h1, g_h1);
    cudaGetSymbolAddress((void**)&h2, g_h2);
    cudaGetSymbolAddress((void**)&h3, g_h3);
    cudaGetSymbolAddress((void**)&h4, g_h4);
    cudaGetSymbolAddress((void**)&h5, g_h5);
    cudaGetSymbolAddress((void**)&h6, g_h6);
    cudaGetSymbolAddress((void**)&h7, g_h7);

    const int TB = TLEN / TT;   // 16 tiles along T
    const long long BSX = (long long)1536 * TLEN;

    const int SM24 = smem_bytes(24);   // ~82 KB -> 2 CTAs/SM (leaf)
    const int SM16 = smem_bytes(16);   // ~58 KB -> 3 CTAs/SM

    cudaFuncSetAttribute(gconv_mma_kernel<24, 20, 20, true>,
                         cudaFuncAttributeMaxDynamicSharedMemorySize, SM24);
    cudaFuncSetAttribute(gconv_mma_kernel<16, 16, 16, true>,
                         cudaFuncAttributeMaxDynamicSharedMemorySize, SM16);
    cudaFuncSetAttribute(gconv_mma_kernel<16, 16, 8, true>,
                         cudaFuncAttributeMaxDynamicSharedMemorySize, SM16);

    // 1. leaf: 64 groups, 20 in/group (padded to 24), 8 out/group
    gconv_mma_kernel<24, 20, 20, true><<<dim3(TB, 64, BATCH), NTHREADS, SM24>>>(
        x, BSX, nullptr, 0, W_leaf, b_leaf, h1, 64);

    // 2. int0: 32 groups, 16 in/group (from 512 ch)
    gconv_mma_kernel<16, 16, 16, true><<<dim3(TB, 32, BATCH), NTHREADS, SM16>>>(
        h1, (long long)512 * TLEN, nullptr, 0, W_int0, b_int0, h2, 32);

    // 3. br: 32 groups, in/group = 8 (h2) + 8 (syn = x channels 1280..1535)
    gconv_mma_kernel<16, 16, 8, true><<<dim3(TB, 32, BATCH), NTHREADS, SM16>>>(
        h2, (long long)256 * TLEN,
        x + (long long)1280 * TLEN, BSX,
        W_br, b_br, h3, 32);

    // 4. int1: 16 groups (256 -> 128)
    gconv_mma_kernel<16, 16, 16, true><<<dim3(TB, 16, BATCH), NTHREADS, SM16>>>(
        h3, (long long)256 * TLEN, nullptr, 0, W_int1, b_int1, h4, 16);

    // 5. int2: 8 groups (128 -> 64)
    gconv_mma_kernel<16, 16, 16, true><<<dim3(TB, 8, BATCH), NTHREADS, SM16>>>(
        h4, (long long)128 * TLEN, nullptr, 0, W_int2, b_int2, h5, 8);

    // 6. int3: 4 groups (64 -> 32)
    gconv_mma_kernel<16, 16, 16, true><<<dim3(TB, 4, BATCH), NTHREADS, SM16>>>(
        h5, (long long)64 * TLEN, nullptr, 0, W_int3, b_int3, h6, 4);

    // 7. int4: 2 groups (32 -> 16)
    gconv_mma_kernel<16, 16, 16, true><<<dim3(TB, 2, BATCH), NTHREADS, SM16>>>(
        h6, (long long)32 * TLEN, nullptr, 0, W_int4, b_int4, h7, 2);

    // 8. root: 1x1 conv 16 -> 1
    root_kernel<<<(BATCH * TLEN + 255) / 256, 256>>>(h7, W_root, b_root, out);
}

// round 15
// speedup vs baseline: 1.8509x; 1.7274x over previous
#include <cuda_runtime.h>
#include <cuda_fp16.h>
#include <cstdint>

// Problem constants
#define BATCH   16
#define TLEN    4096
#define KW      15

// Tiling
#define TT      256      // time tile per CTA
#define NTHREADS 256     // 8 warps; each warp: 2 m16 tiles (32 t)
#define TROWS   272      // staged t' rows: [t0-8, t0+TT+8)
#define NTQ     68       // t-quads
#define SBB     48       // bytes per xT row (fits CINP<=24 fp16, conflict-free)
#define SBW     12       // words per xT row

// ---------------------------------------------------------------------------
// Intermediate activation buffers (static device globals; no runtime alloc)
// ---------------------------------------------------------------------------
__device__ float g_h1[(size_t)BATCH * 512 * TLEN];
__device__ float g_h2[(size_t)BATCH * 256 * TLEN];
__device__ float g_h3[(size_t)BATCH * 256 * TLEN];
__device__ float g_h4[(size_t)BATCH * 128 * TLEN];
__device__ float g_h5[(size_t)BATCH *  64 * TLEN];
__device__ float g_h6[(size_t)BATCH *  32 * TLEN];
__device__ float g_h7[(size_t)BATCH *  16 * TLEN];

// ---------------------------------------------------------------------------
// fp16 / mma / ldmatrix helpers
// ---------------------------------------------------------------------------
__device__ __forceinline__ uint32_t packh2(float a, float b) {
    __half2 h = __floats2half2_rn(a, b);          // a -> low half
    return *reinterpret_cast<uint32_t*>(&h);
}
__device__ __forceinline__ void mma_f16_k16(float* d,
        uint32_t a0, uint32_t a1, uint32_t a2, uint32_t a3,
        uint32_t b0, uint32_t b1) {
    asm("mma.sync.aligned.m16n8k16.row.col.f32.f16.f16.f32 "
        "{%0,%1,%2,%3}, {%4,%5,%6,%7}, {%8,%9}, {%0,%1,%2,%3};"
        : "+f"(d[0]), "+f"(d[1]), "+f"(d[2]), "+f"(d[3])
        : "r"(a0), "r"(a1), "r"(a2), "r"(a3), "r"(b0), "r"(b1));
}
__device__ __forceinline__ void mma_f16_k8(float* d,
        uint32_t a0, uint32_t a1, uint32_t b0) {
    asm("mma.sync.aligned.m16n8k8.row.col.f32.f16.f16.f32 "
        "{%0,%1,%2,%3}, {%4,%5}, {%6}, {%0,%1,%2,%3};"
        : "+f"(d[0]), "+f"(d[1]), "+f"(d[2]), "+f"(d[3])
        : "r"(a0), "r"(a1), "r"(b0));
}
__device__ __forceinline__ void ldsm_x4(uint32_t& r0, uint32_t& r1,
                                        uint32_t& r2, uint32_t& r3, uint32_t addr) {
    asm volatile("ldmatrix.sync.aligned.m8n8.x4.shared.b16 {%0,%1,%2,%3}, [%4];"
                 : "=r"(r0), "=r"(r1), "=r"(r2), "=r"(r3) : "r"(addr));
}
__device__ __forceinline__ void ldsm_x2(uint32_t& r0, uint32_t& r1, uint32_t addr) {
    asm volatile("ldmatrix.sync.aligned.m8n8.x2.shared.b16 {%0,%1}, [%2];"
                 : "=r"(r0), "=r"(r1) : "r"(addr));
}

// ---------------------------------------------------------------------------
// Grouped conv1d K=15 SAME via fp16 split-precision MMA (3 products:
// Ah*Bh + Ah*Bl + Al*Bh; fp16 mantissa = 11 bits, same as the proven tf32
// split -> rel_err ~1e-6).
//   D[t, oc] = sum_{ci, tap} x[ci][t + tap - 7] * W[oc][ci][tap]
// x staged TRANSPOSED as fp16: xT[t'][ci], t' = t - t0 + 8, row stride 48B
// (conflict-free ldmatrix quad pattern). K blocks: CINP/16 k16 blocks via
// m16n8k16 (A frag = ONE ldmatrix.x4 per image) + optional k8 tail via
// m16n8k8 (ldmatrix.x2). B = W^T fp16 pairs; 2 (k16) / 1 (k8) LDS.32 per img.
// Warp w owns t tiles at w*32 and w*32+16. Epilogue = proven R13/R14 D map.
// ---------------------------------------------------------------------------
template<int CINP, int CIN, int C0, bool ACT>
__global__ __launch_bounds__(NTHREADS, 3)
void gconv_mma_kernel(const float* __restrict__ in0, long long bs0,
                      const float* __restrict__ in1, long long bs1,
                      const float* __restrict__ W,
                      const float* __restrict__ bias,
                      float* __restrict__ out, int G)
{
    constexpr int NKB16 = CINP / 16;
    constexpr bool HAS8 = (CINP % 16) == 8;
    constexpr int WPI   = NKB16 * 64 + (HAS8 ? 32 : 0);   // B words per (tap,img)
    static_assert(CINP * 2 <= SBB, "row overflow");

    extern __shared__ uint32_t smem[];
    uint32_t* sxh = smem;                        // TROWS * SBW
    uint32_t* sxl = sxh + TROWS * SBW;           // TROWS * SBW
    uint32_t* swB = sxl + TROWS * SBW;           // KW * 2 * WPI
    float*    sb  = (float*)(swB + KW * 2 * WPI);

    const int b   = blockIdx.z;
    const int g   = blockIdx.y;
    const int t0  = blockIdx.x * TT;
    const int tid = threadIdx.x;
    const int warp = tid >> 5, lane = tid & 31;
    const int gid = lane >> 2;                   // 0..7
    const int tig = lane & 3;                    // 0..3
    const int lrow = (lane & 7) + 8 * ((lane >> 3) & 1);
    const int lcol = (lane >> 4) * 16;           // byte offset of ci-half

    // ---- stage split fp16 weights: swB[(tap*2+img)*WPI + slot]
    // k16 blocks: slot = blk*64 + kp*8 + oc  (kp = k/2, k = ci within block)
    // k8 tail   : slot = NKB16*64 + kp*8 + oc
    for (int i = tid; i < KW * 2 * WPI; i += NTHREADS) {
        int slot = i % WPI;
        int r    = i / WPI;
        int img  = r & 1;
        int tap  = r >> 1;
        int ci, oc;
        if (slot < NKB16 * 64) {
            int blk = slot >> 6, s = slot & 63;
            oc = s & 7;
            ci = blk * 16 + (s >> 3) * 2;
        } else {
            int s = slot - NKB16 * 64;
            oc = s & 7;
            ci = NKB16 * 16 + (s >> 3) * 2;
        }
        float w0 = (ci     < CIN) ? W[((long long)(g * 8 + oc) * CIN + ci    ) * KW + tap] : 0.f;
        float w1 = (ci + 1 < CIN) ? W[((long long)(g * 8 + oc) * CIN + ci + 1) * KW + tap] : 0.f;
        uint32_t v;
        if (img == 0) {
            v = packh2(w0, w1);
        } else {
            float h0 = __half2float(__float2half_rn(w0));
            float h1 = __half2float(__float2half_rn(w1));
            v = packh2(w0 - h0, w1 - h1);
        }
        swB[(tap * 2 + img) * WPI + slot] = v;
    }
    if (tid < 8) sb[tid] = bias[g * 8 + tid];

    // ---- stage x transposed + split fp16: xT[t'][ci] ----
    for (int idx = tid; idx < NTQ * (CINP / 4); idx += NTHREADS) {
        int tc = idx % NTQ;                      // lanes consecutive in t-quad
        int cq = idx / NTQ;
        int tg = t0 - 8 + 4 * tc;
        float4 v[4];
#pragma unroll
        for (int j = 0; j < 4; j++) {
            int ci = cq * 4 + j;
            v[j] = make_float4(0.f, 0.f, 0.f, 0.f);
            if (ci < CIN) {
                const float* src;
                if (C0 == CIN || ci < C0)
                    src = in0 + (long long)b * bs0 + (long long)(g * C0 + ci) * TLEN;
                else
                    src = in1 + (long long)b * bs1 + (long long)(g * (CIN - C0) + (ci - C0)) * TLEN;
                if (tg >= 0 && tg <= TLEN - 4) {
                    v[j] = *(const float4*)(src + tg);
                } else {
                    float* p = (float*)&v[j];
#pragma unroll
                    for (int k = 0; k < 4; k++) {
                        int t = tg + k;
                        if (t >= 0 && t < TLEN) p[k] = src[t];
                    }
                }
            }
        }
#pragma unroll
        for (int k = 0; k < 4; k++) {
            float x0 = ((float*)&v[0])[k];
            float x1 = ((float*)&v[1])[k];
            float x2 = ((float*)&v[2])[k];
            float x3 = ((float*)&v[3])[k];
            float h0 = __half2float(__float2half_rn(x0));
            float h1 = __half2float(__float2half_rn(x1));
            float h2 = __half2float(__float2half_rn(x2));
            float h3 = __half2float(__float2half_rn(x3));
            int off = (4 * tc + k) * SBW + cq * 2;
            sxh[off]     = packh2(x0, x1);
            sxh[off + 1] = packh2(x2, x3);
            sxl[off]     = packh2(x0 - h0, x1 - h1);
            sxl[off + 1] = packh2(x2 - h2, x3 - h3);
        }
    }
    __syncthreads();

    // ---- compute ----
    float d0[4] = {0.f, 0.f, 0.f, 0.f};
    float d1[4] = {0.f, 0.f, 0.f, 0.f};

    uint32_t axh = (uint32_t)__cvta_generic_to_shared(sxh)
                 + (uint32_t)((warp * 32 + 1 + lrow) * SBB + lcol);
    uint32_t axl = axh + (uint32_t)(TROWS * SBB);

#pragma unroll 1
    for (int tap = 0; tap < KW; tap++) {
        const uint32_t* wbh = swB + (tap * 2 + 0) * WPI;
        const uint32_t* wbl = swB + (tap * 2 + 1) * WPI;
        uint32_t roff = (uint32_t)(tap * SBB);

#pragma unroll
        for (int blk = 0; blk < NKB16; blk++) {
            int bidx = blk * 64 + tig * 8 + gid;
            uint32_t bh0 = wbh[bidx], bh1 = wbh[bidx + 32];
            uint32_t bl0 = wbl[bidx], bl1 = wbl[bidx + 32];
            uint32_t coff = roff + (uint32_t)(blk * 32);
            {   // tile 0
                uint32_t ah0, ah1, ah2, ah3, al0, al1, al2, al3;
                ldsm_x4(ah0, ah1, ah2, ah3, axh + coff);
                ldsm_x4(al0, al1, al2, al3, axl + coff);
                mma_f16_k16(d0, ah0, ah1, ah2, ah3, bh0, bh1);
                mma_f16_k16(d0, ah0, ah1, ah2, ah3, bl0, bl1);
                mma_f16_k16(d0, al0, al1, al2, al3, bh0, bh1);
            }
            {   // tile 1 (+16 t rows)
                uint32_t toff = coff + (uint32_t)(16 * SBB);
                uint32_t ah0, ah1, ah2, ah3, al0, al1, al2, al3;
                ldsm_x4(ah0, ah1, ah2, ah3, axh + toff);
                ldsm_x4(al0, al1, al2, al3, axl + toff);
                mma_f16_k16(d1, ah0, ah1, ah2, ah3, bh0, bh1);
                mma_f16_k16(d1, ah0, ah1, ah2, ah3, bl0, bl1);
                mma_f16_k16(d1, al0, al1, al2, al3, bh0, bh1);
            }
        }
        if (HAS8) {
            int bidx = NKB16 * 64 + tig * 8 + gid;
            uint32_t bh0 = wbh[bidx];
            uint32_t bl0 = wbl[bidx];
            uint32_t coff = roff + (uint32_t)(NKB16 * 32);
            {   // tile 0
                uint32_t ah0, ah1, al0, al1;
                ldsm_x2(ah0, ah1, axh + coff);
                ldsm_x2(al0, al1, axl + coff);
                mma_f16_k8(d0, ah0, ah1, bh0);
                mma_f16_k8(d0, ah0, ah1, bl0);
                mma_f16_k8(d0, al0, al1, bh0);
            }
            {   // tile 1
                uint32_t toff = coff + (uint32_t)(16 * SBB);
                uint32_t ah0, ah1, al0, al1;
                ldsm_x2(ah0, ah1, axh + toff);
                ldsm_x2(al0, al1, axl + toff);
                mma_f16_k8(d1, ah0, ah1, bh0);
                mma_f16_k8(d1, ah0, ah1, bl0);
                mma_f16_k8(d1, al0, al1, bh0);
            }
        }
    }

    // ---- epilogue: bias + leaky relu (proven D map) ----
    const float bv0 = sb[2 * tig];
    const float bv1 = sb[2 * tig + 1];
    float* obase = out + ((long long)(b * G + g) * 8) * TLEN + t0 + warp * 32;
    float* o0 = obase + (long long)(2 * tig) * TLEN;
    float* o1 = obase + (long long)(2 * tig + 1) * TLEN;

    auto act = [](float v, bool on) { return on ? (v > 0.f ? v : 0.01f * v) : v; };
    o0[gid]      = act(d0[0] + bv0, ACT);
    o1[gid]      = act(d0[1] + bv1, ACT);
    o0[gid + 8]  = act(d0[2] + bv0, ACT);
    o1[gid + 8]  = act(d0[3] + bv1, ACT);
    o0[gid + 16] = act(d1[0] + bv0, ACT);
    o1[gid + 16] = act(d1[1] + bv1, ACT);
    o0[gid + 24] = act(d1[2] + bv0, ACT);
    o1[gid + 24] = act(d1[3] + bv1, ACT);
}

// ---------------------------------------------------------------------------
// Root: 1x1 conv over 16 channels -> 1 channel (no activation)
// ---------------------------------------------------------------------------
__global__ void root_kernel(const float* __restrict__ h,
                            const float* __restrict__ w,
                            const float* __restrict__ bias,
                            float* __restrict__ out)
{
    int idx = blockIdx.x * blockDim.x + threadIdx.x;
    if (idx >= BATCH * TLEN) return;
    int b = idx / TLEN;
    int t = idx - b * TLEN;
    const float* hp = h + (long long)b * 16 * TLEN + t;
    float s = bias[0];
#pragma unroll
    for (int c = 0; c < 16; c++)
        s = fmaf(__ldg(&w[c]), hp[(long long)c * TLEN], s);
    out[idx] = s;
}

// ---------------------------------------------------------------------------
// Launch
// ---------------------------------------------------------------------------
static inline int wpi(int cinp) { return (cinp / 16) * 64 + ((cinp % 16) / 8) * 32; }
static inline int smem_bytes(int cinp) {
    return (2 * TROWS * SBW + KW * 2 * wpi(cinp) + 8) * 4;
}

extern "C" void kernel_launch(void* const* d_in, const int* in_sizes, int n_in,
                              void* d_out, int out_size)
{
    const float* x      = (const float*)d_in[0];
    const float* W_leaf = (const float*)d_in[1];
    const float* b_leaf = (const float*)d_in[2];
    const float* W_int0 = (const float*)d_in[3];
    const float* b_int0 = (const float*)d_in[4];
    const float* W_br   = (const float*)d_in[5];
    const float* b_br   = (const float*)d_in[6];
    const float* W_int1 = (const float*)d_in[7];
    const float* b_int1 = (const float*)d_in[8];
    const float* W_int2 = (const float*)d_in[9];
    const float* b_int2 = (const float*)d_in[10];
    const float* W_int3 = (const float*)d_in[11];
    const float* b_int3 = (const float*)d_in[12];
    const float* W_int4 = (const float*)d_in[13];
    const float* b_int4 = (const float*)d_in[14];
    const float* W_root = (const float*)d_in[15];
    const float* b_root = (const float*)d_in[16];
    float* out = (float*)d_out;

    float *h1, *h2, *h3, *h4, *h5, *h6, *h7;
    cudaGetSymbolAddress((void**)&h1, g_h1);
    cudaGetSymbolAddress((void**)&h2, g_h2);
    cudaGetSymbolAddress((void**)&h3, g_h3);
    cudaGetSymbolAddress((void**)&h4, g_h4);
    cudaGetSymbolAddress((void**)&h5, g_h5);
    cudaGetSymbolAddress((void**)&h6, g_h6);
    cudaGetSymbolAddress((void**)&h7, g_h7);

    const int TB = TLEN / TT;   // 16 tiles along T
    const long long BSX = (long long)1536 * TLEN;

    const int SM24 = smem_bytes(24);   // leaf: k16 + k8 tail  (~37.5 KB)
    const int SM16 = smem_bytes(16);   // ints: one k16 block (~34 KB)

    cudaFuncSetAttribute(gconv_mma_kernel<24, 20, 20, true>,
                         cudaFuncAttributeMaxDynamicSharedMemorySize, SM24);
    cudaFuncSetAttribute(gconv_mma_kernel<16, 16, 16, true>,
                         cudaFuncAttributeMaxDynamicSharedMemorySize, SM16);
    cudaFuncSetAttribute(gconv_mma_kernel<16, 16, 8, true>,
                         cudaFuncAttributeMaxDynamicSharedMemorySize, SM16);

    // 1. leaf: 64 groups, 20 in/group (padded to 24 = k16 + k8), 8 out/group
    gconv_mma_kernel<24, 20, 20, true><<<dim3(TB, 64, BATCH), NTHREADS, SM24>>>(
        x, BSX, nullptr, 0, W_leaf, b_leaf, h1, 64);

    // 2. int0: 32 groups, 16 in/group (from 512 ch)
    gconv_mma_kernel<16, 16, 16, true><<<dim3(TB, 32, BATCH), NTHREADS, SM16>>>(
        h1, (long long)512 * TLEN, nullptr, 0, W_int0, b_int0, h2, 32);

    // 3. br: 32 groups, in/group = 8 (h2) + 8 (syn = x channels 1280..1535)
    gconv_mma_kernel<16, 16, 8, true><<<dim3(TB, 32, BATCH), NTHREADS, SM16>>>(
        h2, (long long)256 * TLEN,
        x + (long long)1280 * TLEN, BSX,
        W_br, b_br, h3, 32);

    // 4. int1: 16 groups (256 -> 128)
    gconv_mma_kernel<16, 16, 16, true><<<dim3(TB, 16, BATCH), NTHREADS, SM16>>>(
        h3, (long long)256 * TLEN, nullptr, 0, W_int1, b_int1, h4, 16);

    // 5. int2: 8 groups (128 -> 64)
    gconv_mma_kernel<16, 16, 16, true><<<dim3(TB, 8, BATCH), NTHREADS, SM16>>>(
        h4, (long long)128 * TLEN, nullptr, 0, W_int2, b_int2, h5, 8);

    // 6. int3: 4 groups (64 -> 32)
    gconv_mma_kernel<16, 16, 16, true><<<dim3(TB, 4, BATCH), NTHREADS, SM16>>>(
        h5, (long long)64 * TLEN, nullptr, 0, W_int3, b_int3, h6, 4);

    // 7. int4: 2 groups (32 -> 16)
    gconv_mma_kernel<16, 16, 16, true><<<dim3(TB, 2, BATCH), NTHREADS, SM16>>>(
        h6, (long long)32 * TLEN, nullptr, 0, W_int4, b_int4, h7, 2);

    // 8. root: 1x1 conv 16 -> 1
    root_kernel<<<(BATCH * TLEN + 255) / 256, 256>>>(h7, W_root, b_root, out);
}